// round 8
// baseline (speedup 1.0000x reference)
#include <cuda_runtime.h>

#define LSN 4096   // layer size
#define NIN 1024   // input length (x columns)
#define BATN 64    // batch
#define FCN 512    // fc slice
#define NCLS 10

#define KCH1 4
#define KC1 256    // KCH1*KC1 = 1024
#define KCH2 16
#define KC2 256    // KCH2*KC2 = 4096

#define DCH 32           // diag-scan chunk height
#define DMAX 5120        // >= LSN + NIN - 1
#define NCH1 (NIN / DCH) // 32
#define NCH2 (FCN / DCH) // 16

#define GRID 444         // 148 SMs x 3 blocks (co-resident by launch bounds)
#define NTHR 256

// ---------------- static scratch (no allocations allowed) ----------------
// g_d rows: 0=da1 1=1/da1 2=db1 3=1/db1 4=da2 5=1/da2 6=db2 7=1/db2
__device__ float g_d[8][LSN];
__device__ float g_buf1[NIN * LSN];        // A1^T then locally-scanned C1^T : rows=k, cols=j
__device__ float g_buf2[FCN * LSN];        // A2 then locally-scanned C2     : rows=j, cols=k
__device__ float g_z1[BATN * NIN];         // x * db1
__device__ float g_z2[BATN * LSN];         // relu(layer1) scaled by db2
__device__ float g_y1p[KCH1 * BATN * LSN]; // K-split partials layer 1
__device__ float g_y2p[KCH2 * BATN * FCN]; // K-split partials layer 2
__device__ float g_T1t[DMAX * NCH1];       // per-chunk diagonal totals, transposed [d][q]
__device__ float g_T2t[DMAX * NCH2];
__device__ float g_O1[NCH1][DMAX];         // per-chunk diagonal prefix offsets [q][d]
__device__ float g_O2[NCH2][DMAX];
__device__ unsigned int g_cnt1[64];        // per-jblk completion counters for S4 epilogue
__device__ unsigned int g_bar[8];          // monotonic grid-barrier counters (never reset)

// ---------------- software grid barrier (monotonic counters, replay-safe) ----------------
__device__ __forceinline__ void grid_barrier(int b) {
    __syncthreads();
    __threadfence();
    if (threadIdx.x == 0) {
        unsigned int G = gridDim.x;
        unsigned int old = atomicAdd(&g_bar[b], 1u);
        unsigned int target = (old / G + 1u) * G;
        while (*(volatile unsigned int*)&g_bar[b] < target) __nanosleep(32);
        __threadfence();
    }
    __syncthreads();
}

// ---------------- stage bodies ----------------

// S0: cumprod d = [1, cumprod(subd)] + reciprocals (256 threads, 16 elems/thread)
__device__ __forceinline__ void scan_body(int w, const float* __restrict__ s, float* sm) {
    float* d  = g_d[2 * w];
    float* di = g_d[2 * w + 1];
    int t = threadIdx.x, lane = t & 31, warp = t >> 5;
    int base = 16 * t;
    float v[16];
    float prod = 1.f;
    #pragma unroll
    for (int i = 0; i < 16; ++i) {
        v[i] = (base + i < LSN - 1) ? s[base + i] : 1.f;
        prod *= v[i];
    }
    float sp = prod;
    #pragma unroll
    for (int off = 1; off < 32; off <<= 1) {
        float n = __shfl_up_sync(0xffffffffu, sp, off);
        if (lane >= off) sp *= n;
    }
    if (lane == 31) sm[warp] = sp;
    __syncthreads();
    if (warp == 0) {
        float wv = (lane < 8) ? sm[lane] : 1.f;
        #pragma unroll
        for (int off = 1; off < 8; off <<= 1) {
            float n = __shfl_up_sync(0xffffffffu, wv, off);
            if (lane >= off) wv *= n;
        }
        if (lane < 8) sm[lane] = wv;
    }
    __syncthreads();
    float wb = (warp == 0) ? 1.f : sm[warp - 1];
    float ep = __shfl_up_sync(0xffffffffu, sp, 1);
    if (lane == 0) ep = 1.f;
    float run = wb * ep;
    #pragma unroll
    for (int i = 0; i < 16; ++i) {
        d[base + i]  = run;
        di[base + i] = 1.f / run;
        run *= v[i];
    }
}

// S1: rank-K build: out[r,c] = (1/dR[r])(1/dC[c]) sum_i P[i,r] Q[i,c]
template<int KD, int IR, int IC>
__device__ __forceinline__ void gemmA_body(const float* __restrict__ P, const float* __restrict__ Q,
                                           float* __restrict__ out,
                                           float (*shP)[64], float (*shQ)[64],
                                           int r0, int c0) {
    int tid = threadIdx.x;
    int tx = tid & 15, ty = tid >> 4;
    float acc[4][4] = {};
    for (int i0 = 0; i0 < KD; i0 += 16) {
        {
            int kk = tid >> 4, rc4 = (tid & 15) * 4;
            *reinterpret_cast<float4*>(&shP[kk][rc4]) =
                *reinterpret_cast<const float4*>(P + (i0 + kk) * LSN + r0 + rc4);
            *reinterpret_cast<float4*>(&shQ[kk][rc4]) =
                *reinterpret_cast<const float4*>(Q + (i0 + kk) * LSN + c0 + rc4);
        }
        __syncthreads();
        #pragma unroll
        for (int kk = 0; kk < 16; ++kk) {
            float a[4], b[4];
            #pragma unroll
            for (int u = 0; u < 4; ++u) a[u] = shP[kk][ty * 4 + u];
            #pragma unroll
            for (int v = 0; v < 4; ++v) b[v] = shQ[kk][tx * 4 + v];
            #pragma unroll
            for (int u = 0; u < 4; ++u)
                #pragma unroll
                for (int v = 0; v < 4; ++v) acc[u][v] += a[u] * b[v];
        }
        __syncthreads();
    }
    #pragma unroll
    for (int u = 0; u < 4; ++u) {
        int r = r0 + ty * 4 + u;
        float ir = g_d[IR][r];
        int c = c0 + tx * 4;
        float4 o;
        o.x = ir * g_d[IC][c + 0] * acc[u][0];
        o.y = ir * g_d[IC][c + 1] * acc[u][1];
        o.z = ir * g_d[IC][c + 2] * acc[u][2];
        o.w = ir * g_d[IC][c + 3] * acc[u][3];
        *reinterpret_cast<float4*>(out + r * LSN + c) = o;
    }
}

// S2: chunk-local diagonal cumsum; totals -> Tt[d][q]
template<int R, int NCH, int OB>
__device__ __forceinline__ void diag_local_body(int xblk, int q) {
    float* buf = OB ? g_buf2 : g_buf1;
    float* Tt = OB ? g_T2t : g_T1t;
    constexpr int NSTART = LSN + DCH - 1;
    int j = xblk * 256 + threadIdx.x;
    if (j >= NSTART) return;
    int r0, c0;
    if (j < LSN) { r0 = q * DCH; c0 = j; }
    else         { r0 = q * DCH + (j - LSN + 1); c0 = 0; }
    int lenA = DCH - (r0 - q * DCH);
    int lenB = LSN - c0;
    int len = lenA < lenB ? lenA : lenB;
    int idx = r0 * LSN + c0;
    float acc = 0.f;
    #pragma unroll 8
    for (int s = 0; s < len; ++s) {
        acc += buf[idx];
        buf[idx] = acc;
        idx += LSN + 1;
    }
    Tt[(c0 - r0 + (R - 1)) * NCH + q] = acc;
}

// S3: register prefix-scan of chunk totals -> O[q][d]
template<int R, int NCH, int OB>
__device__ __forceinline__ void diag_offsets_body(int xblk) {
    const float* Tt = OB ? g_T2t : g_T1t;
    float (*O)[DMAX] = OB ? g_O2 : g_O1;
    int d = xblk * 256 + threadIdx.x;
    if (d >= R + LSN - 1) return;
    int dd = d - (R - 1);
    float t[NCH];
    const float4* p = reinterpret_cast<const float4*>(Tt + d * NCH);
    #pragma unroll
    for (int i = 0; i < NCH / 4; ++i) {
        float4 v = p[i];
        t[4 * i + 0] = v.x; t[4 * i + 1] = v.y;
        t[4 * i + 2] = v.z; t[4 * i + 3] = v.w;
    }
    float acc = 0.f;
    #pragma unroll
    for (int q = 0; q < NCH; ++q) {
        O[q][d] = acc;
        int rt = q * DCH, rb = rt + DCH - 1;
        if ((rt + dd < LSN) && (rb + dd >= 0)) acc += t[q];
    }
}

// S4/S5: apply GEMM: OUT(64 x N) = A(64 x KT) @ C, C[r,c] = buf[r,c] + O[r/DCH][c-r+R-1]
template<int LAYER>
__device__ __forceinline__ void gemm64_body(int jblk, int kblk,
                                            float (*shA)[36], float (*shB)[68]) {
    constexpr int N  = (LAYER == 1) ? LSN : FCN;
    constexpr int KT = (LAYER == 1) ? NIN : LSN;
    constexpr int KC = (LAYER == 1) ? KC1 : KC2;
    constexpr int R  = (LAYER == 1) ? NIN : FCN;
    constexpr int BT = (LAYER == 1) ? 0 : 1;
    const float* A = (LAYER == 1) ? g_z1 : g_z2;
    const float* B = (LAYER == 1) ? g_buf1 : g_buf2;
    float (*O)[DMAX] = (LAYER == 1) ? g_O1 : g_O2;
    float* OUT = (LAYER == 1) ? g_y1p : g_y2p;
    int j0 = jblk * 64;
    int k0 = kblk * KC;
    int tid = threadIdx.x;
    int tx = tid & 15, ty = tid >> 4;
    float acc[4][4] = {};
    for (int ks = 0; ks < KC; ks += 32) {
        int kb = k0 + ks;
        #pragma unroll
        for (int it = 0; it < 2; ++it) {
            int e = it * 256 + tid;
            int bb = e >> 3, kk4 = (e & 7) * 4;
            *reinterpret_cast<float4*>(&shA[bb][kk4]) =
                *reinterpret_cast<const float4*>(A + bb * KT + kb + kk4);
        }
        if (BT == 0) {
            #pragma unroll
            for (int it = 0; it < 2; ++it) {
                int e = it * 256 + tid;
                int kk = e >> 4, jj4 = (e & 15) * 4;
                int kg = kb + kk;
                float4 v = *reinterpret_cast<const float4*>(B + kg * LSN + j0 + jj4);
                const float* Oq = O[kg >> 5];   // DCH = 32
                int d = (j0 + jj4) - kg + (R - 1);
                v.x += Oq[d]; v.y += Oq[d + 1]; v.z += Oq[d + 2]; v.w += Oq[d + 3];
                *reinterpret_cast<float4*>(&shB[kk][jj4]) = v;
            }
        } else {
            #pragma unroll
            for (int it = 0; it < 2; ++it) {
                int e = it * 256 + tid;
                int jj = e >> 3, kk4 = (e & 7) * 4;
                int jg = j0 + jj;
                float4 v = *reinterpret_cast<const float4*>(B + jg * KT + kb + kk4);
                const float* Oq = O[jg >> 5];
                int d = (kb + kk4) - jg + (R - 1);
                shB[kk4 + 0][jj] = v.x + Oq[d];
                shB[kk4 + 1][jj] = v.y + Oq[d + 1];
                shB[kk4 + 2][jj] = v.z + Oq[d + 2];
                shB[kk4 + 3][jj] = v.w + Oq[d + 3];
            }
        }
        __syncthreads();
        #pragma unroll
        for (int kk = 0; kk < 32; ++kk) {
            float a[4], b[4];
            #pragma unroll
            for (int u = 0; u < 4; ++u) a[u] = shA[ty * 4 + u][kk];
            #pragma unroll
            for (int v = 0; v < 4; ++v) b[v] = shB[kk][tx * 4 + v];
            #pragma unroll
            for (int u = 0; u < 4; ++u)
                #pragma unroll
                for (int v = 0; v < 4; ++v) acc[u][v] += a[u] * b[v];
        }
        __syncthreads();
    }
    #pragma unroll
    for (int u = 0; u < 4; ++u) {
        int bb = ty * 4 + u;
        float4 o = make_float4(acc[u][0], acc[u][1], acc[u][2], acc[u][3]);
        *reinterpret_cast<float4*>(OUT + kblk * (64 * N) + bb * N + j0 + tx * 4) = o;
    }
}

// ---------------- the whole pipeline: ONE persistent kernel ----------------
__global__ void __launch_bounds__(NTHR, 3) mono_kernel(
    const float* __restrict__ x,
    const float* __restrict__ G1, const float* __restrict__ H1,
    const float* __restrict__ sA1, const float* __restrict__ sB1,
    const float* __restrict__ bias1,
    const float* __restrict__ G2, const float* __restrict__ H2,
    const float* __restrict__ sA2, const float* __restrict__ sB2,
    const float* __restrict__ bias2,
    const float* __restrict__ W, const float* __restrict__ bl,
    float* __restrict__ out)
{
    __shared__ float sm[4608];                 // 18 KB pool, aliased per stage
    __shared__ unsigned int sh_isLast;
    const int bid = blockIdx.x;
    const int tid = threadIdx.x;
    const int G = GRID;

    // ---- S0: cumprod scans ----
    for (int t = bid; t < 4; t += G) {
        const float* s = (t == 0) ? sA1 : (t == 1) ? sB1 : (t == 2) ? sA2 : sB2;
        scan_body(t, s, sm);
    }
    grid_barrier(0);

    // ---- S1: gemmA1 (1024) + gemmA2 (512) + z1 prep (64) ----
    {
        float (*shP)[64] = reinterpret_cast<float(*)[64]>(sm);
        float (*shQ)[64] = reinterpret_cast<float(*)[64]>(sm + 1024);
        for (int t = bid; t < 1600; t += G) {
            if (t < 1024) {
                gemmA_body<48, 3, 1>(H1, G1, g_buf1, shP, shQ, (t >> 6) * 64, (t & 63) * 64);
            } else if (t < 1536) {
                int e = t - 1024;
                gemmA_body<16, 5, 7>(G2, H2, g_buf2, shP, shQ, (e >> 6) * 64, (e & 63) * 64);
            } else {
                int b = t - 1536;                       // batch row
                const float4* xv = reinterpret_cast<const float4*>(x + b * NIN);
                float4* zv = reinterpret_cast<float4*>(g_z1 + b * NIN);
                const float4* dv = reinterpret_cast<const float4*>(g_d[2]);
                float4 xx = xv[tid], dd = dv[tid];
                zv[tid] = make_float4(xx.x * dd.x, xx.y * dd.y, xx.z * dd.z, xx.w * dd.w);
            }
        }
    }
    grid_barrier(1);

    // ---- S2: chunk-local diagonal cumsums (544 + 272 tasks) ----
    for (int t = bid; t < 17 * NCH1 + 17 * NCH2; t += G) {
        if (t < 17 * NCH1) diag_local_body<NIN, NCH1, 0>(t % 17, t / 17);
        else { int e = t - 17 * NCH1; diag_local_body<FCN, NCH2, 1>(e % 17, e / 17); }
    }
    grid_barrier(2);

    // ---- S3: diagonal offsets (20 + 18 tasks) + counter reset ----
    for (int t = bid; t < 39; t += G) {
        if (t < 20)      diag_offsets_body<NIN, NCH1, 0>(t);
        else if (t < 38) diag_offsets_body<FCN, NCH2, 1>(t - 20);
        else if (tid < 64) g_cnt1[tid] = 0u;
    }
    grid_barrier(3);

    // ---- S4: gemm64_1 (256 tasks) with fused per-jblk reduce1 epilogue ----
    {
        float (*shA)[36] = reinterpret_cast<float(*)[36]>(sm);
        float (*shB)[68] = reinterpret_cast<float(*)[68]>(sm + 2304);
        for (int t = bid; t < 256; t += G) {
            int jblk = t & 63, kblk = t >> 6;
            gemm64_body<1>(jblk, kblk, shA, shB);
            __threadfence();
            if (tid == 0)
                sh_isLast = (atomicAdd(&g_cnt1[jblk], 1u) == KCH1 - 1u);
            __syncthreads();
            if (sh_isLast) {
                int j0 = jblk * 64;
                #pragma unroll
                for (int e = 0; e < 4; ++e) {
                    int lin = e * 256 + tid;
                    int b = lin >> 4, jj4 = (lin & 15) * 4;
                    int j = j0 + jj4;
                    float4 s = *reinterpret_cast<const float4*>(&g_y1p[b * LSN + j]);
                    #pragma unroll
                    for (int c = 1; c < KCH1; ++c) {
                        float4 p = *reinterpret_cast<const float4*>(&g_y1p[c * (BATN * LSN) + b * LSN + j]);
                        s.x += p.x; s.y += p.y; s.z += p.z; s.w += p.w;
                    }
                    float4 da = *reinterpret_cast<const float4*>(&g_d[0][j]);
                    float4 db = *reinterpret_cast<const float4*>(&g_d[6][j]);
                    float4 bi = *reinterpret_cast<const float4*>(&bias1[j]);
                    float4 o;
                    o.x = fmaxf(da.x * s.x + bi.x, 0.f) * db.x;
                    o.y = fmaxf(da.y * s.y + bi.y, 0.f) * db.y;
                    o.z = fmaxf(da.z * s.z + bi.z, 0.f) * db.z;
                    o.w = fmaxf(da.w * s.w + bi.w, 0.f) * db.w;
                    *reinterpret_cast<float4*>(&g_z2[b * LSN + j]) = o;
                }
            }
            __syncthreads();
        }
    }
    grid_barrier(4);

    // ---- S5: gemm64_2 (128 tasks) ----
    {
        float (*shA)[36] = reinterpret_cast<float(*)[36]>(sm);
        float (*shB)[68] = reinterpret_cast<float(*)[68]>(sm + 2304);
        for (int t = bid; t < 128; t += G)
            gemm64_body<2>(t & 7, t >> 3, shA, shB);
    }
    grid_barrier(5);

    // ---- S6: tail — reduce2 + logits (64 tasks) ----
    for (int t = bid; t < BATN; t += G) {
        float* h = sm;                           // 512 floats
        for (int j = tid; j < FCN; j += NTHR) {
            float s = 0.f;
            #pragma unroll
            for (int c = 0; c < KCH2; ++c) s += g_y2p[c * (BATN * FCN) + t * FCN + j];
            float v = g_d[4][j] * s + bias2[j];
            h[j] = v > 0.f ? v : 0.f;
        }
        __syncthreads();
        int warp = tid >> 5, lane = tid & 31;
        for (int c = warp; c < NCLS; c += 8) {
            const float* wrow = W + c * FCN;
            float s = 0.f;
            #pragma unroll 4
            for (int j = lane; j < FCN; j += 32) s += h[j] * wrow[j];
            #pragma unroll
            for (int off = 16; off; off >>= 1) s += __shfl_xor_sync(0xffffffffu, s, off);
            if (lane == 0) out[t * NCLS + c] = s + bl[c];
        }
        __syncthreads();
    }
}

// ---------------- launch ----------------
extern "C" void kernel_launch(void* const* d_in, const int* in_sizes, int n_in,
                              void* d_out, int out_size) {
    (void)in_sizes; (void)n_in; (void)out_size;
    const float* x      = (const float*)d_in[0];
    const float* G1     = (const float*)d_in[1];
    const float* H1     = (const float*)d_in[2];
    const float* sA1    = (const float*)d_in[3];
    const float* sB1    = (const float*)d_in[4];
    const float* bias1  = (const float*)d_in[5];
    const float* G2     = (const float*)d_in[6];
    const float* H2     = (const float*)d_in[7];
    const float* sA2    = (const float*)d_in[8];
    const float* sB2    = (const float*)d_in[9];
    const float* bias2  = (const float*)d_in[10];
    const float* W      = (const float*)d_in[11];
    const float* bl     = (const float*)d_in[12];
    float* out = (float*)d_out;

    mono_kernel<<<GRID, NTHR>>>(x, G1, H1, sA1, sB1, bias1,
                                G2, H2, sA2, sB2, bias2, W, bl, out);
}

// round 9
// speedup vs baseline: 1.0841x; 1.0841x over previous
#include <cuda_runtime.h>

#define LSN 4096   // layer size
#define NIN 1024   // input length (x columns)
#define BATN 64    // batch
#define FCN 512    // fc slice
#define NCLS 10

#define KCH1 4
#define KC1 256    // KCH1*KC1 = 1024
#define KCH2 16
#define KC2 256    // KCH2*KC2 = 4096

#define DCH 32           // diag-scan chunk height
#define DMAX 5120        // >= LSN + NIN - 1
#define NCH1 (NIN / DCH) // 32
#define NCH2 (FCN / DCH) // 16

#define GRID_A 408       // <= 444 co-resident (256 thr, <=85 regs, 8KB smem)
#define GRID_B 296       // 148 SMs x 2 blocks (256 thr, <=128 regs, 18KB smem)
#define NTHR 256

// ---------------- static scratch (no allocations allowed) ----------------
// g_d rows: 0=da1 1=1/da1 2=db1 3=1/db1 4=da2 5=1/da2 6=db2 7=1/db2
__device__ float g_d[8][LSN];
__device__ float g_buf1[NIN * LSN];        // A1^T then locally-scanned C1^T : rows=k, cols=j
__device__ float g_buf2[FCN * LSN];        // A2 then locally-scanned C2     : rows=j, cols=k
__device__ float g_z1[BATN * NIN];         // x * db1
__device__ float g_z2[BATN * LSN];         // relu(layer1) scaled by db2
__device__ float g_y1p[KCH1 * BATN * LSN]; // K-split partials layer 1
__device__ float g_y2p[KCH2 * BATN * FCN]; // K-split partials layer 2
__device__ float g_T1t[DMAX * NCH1];       // per-chunk diagonal totals, transposed [d][q]
__device__ float g_T2t[DMAX * NCH2];
__device__ float g_O1[NCH1][DMAX];         // per-chunk diagonal prefix offsets [q][d]
__device__ float g_O2[NCH2][DMAX];
__device__ unsigned int g_cnt1[64];        // per-jblk completion counters (reset in kernel A)
__device__ unsigned int g_bar[8];          // monotonic grid-barrier counters (never reset)

// ---------------- software grid barrier (monotonic counters, replay-safe) ----------------
__device__ __forceinline__ void grid_barrier(int b) {
    __syncthreads();
    __threadfence();
    if (threadIdx.x == 0) {
        unsigned int G = gridDim.x;
        unsigned int old = atomicAdd(&g_bar[b], 1u);
        unsigned int target = (old / G + 1u) * G;
        while (*(volatile unsigned int*)&g_bar[b] < target) __nanosleep(32);
        __threadfence();
    }
    __syncthreads();
}

// ---------------- stage bodies ----------------

// S0: cumprod d = [1, cumprod(subd)] + reciprocals (256 threads, 16 elems/thread)
__device__ __forceinline__ void scan_body(int w, const float* __restrict__ s, float* sm) {
    float* d  = g_d[2 * w];
    float* di = g_d[2 * w + 1];
    int t = threadIdx.x, lane = t & 31, warp = t >> 5;
    int base = 16 * t;
    float v[16];
    float prod = 1.f;
    #pragma unroll
    for (int i = 0; i < 16; ++i) {
        v[i] = (base + i < LSN - 1) ? s[base + i] : 1.f;
        prod *= v[i];
    }
    float sp = prod;
    #pragma unroll
    for (int off = 1; off < 32; off <<= 1) {
        float n = __shfl_up_sync(0xffffffffu, sp, off);
        if (lane >= off) sp *= n;
    }
    if (lane == 31) sm[warp] = sp;
    __syncthreads();
    if (warp == 0) {
        float wv = (lane < 8) ? sm[lane] : 1.f;
        #pragma unroll
        for (int off = 1; off < 8; off <<= 1) {
            float n = __shfl_up_sync(0xffffffffu, wv, off);
            if (lane >= off) wv *= n;
        }
        if (lane < 8) sm[lane] = wv;
    }
    __syncthreads();
    float wb = (warp == 0) ? 1.f : sm[warp - 1];
    float ep = __shfl_up_sync(0xffffffffu, sp, 1);
    if (lane == 0) ep = 1.f;
    float run = wb * ep;
    #pragma unroll
    for (int i = 0; i < 16; ++i) {
        d[base + i]  = run;
        di[base + i] = 1.f / run;
        run *= v[i];
    }
}

// S1: rank-K build: out[r,c] = (1/dR[r])(1/dC[c]) sum_i P[i,r] Q[i,c]
template<int KD, int IR, int IC>
__device__ __forceinline__ void gemmA_body(const float* __restrict__ P, const float* __restrict__ Q,
                                           float* __restrict__ out,
                                           float (*shP)[64], float (*shQ)[64],
                                           int r0, int c0) {
    int tid = threadIdx.x;
    int tx = tid & 15, ty = tid >> 4;
    float acc[4][4] = {};
    for (int i0 = 0; i0 < KD; i0 += 16) {
        {
            int kk = tid >> 4, rc4 = (tid & 15) * 4;
            *reinterpret_cast<float4*>(&shP[kk][rc4]) =
                *reinterpret_cast<const float4*>(P + (i0 + kk) * LSN + r0 + rc4);
            *reinterpret_cast<float4*>(&shQ[kk][rc4]) =
                *reinterpret_cast<const float4*>(Q + (i0 + kk) * LSN + c0 + rc4);
        }
        __syncthreads();
        #pragma unroll
        for (int kk = 0; kk < 16; ++kk) {
            float a[4], b[4];
            #pragma unroll
            for (int u = 0; u < 4; ++u) a[u] = shP[kk][ty * 4 + u];
            #pragma unroll
            for (int v = 0; v < 4; ++v) b[v] = shQ[kk][tx * 4 + v];
            #pragma unroll
            for (int u = 0; u < 4; ++u)
                #pragma unroll
                for (int v = 0; v < 4; ++v) acc[u][v] += a[u] * b[v];
        }
        __syncthreads();
    }
    #pragma unroll
    for (int u = 0; u < 4; ++u) {
        int r = r0 + ty * 4 + u;
        float ir = g_d[IR][r];
        int c = c0 + tx * 4;
        float4 o;
        o.x = ir * g_d[IC][c + 0] * acc[u][0];
        o.y = ir * g_d[IC][c + 1] * acc[u][1];
        o.z = ir * g_d[IC][c + 2] * acc[u][2];
        o.w = ir * g_d[IC][c + 3] * acc[u][3];
        *reinterpret_cast<float4*>(out + r * LSN + c) = o;
    }
}

// S2: chunk-local diagonal cumsum; totals -> Tt[d][q]
template<int R, int NCH, int OB>
__device__ __forceinline__ void diag_local_body(int xblk, int q) {
    float* buf = OB ? g_buf2 : g_buf1;
    float* Tt = OB ? g_T2t : g_T1t;
    constexpr int NSTART = LSN + DCH - 1;
    int j = xblk * 256 + threadIdx.x;
    if (j >= NSTART) return;
    int r0, c0;
    if (j < LSN) { r0 = q * DCH; c0 = j; }
    else         { r0 = q * DCH + (j - LSN + 1); c0 = 0; }
    int lenA = DCH - (r0 - q * DCH);
    int lenB = LSN - c0;
    int len = lenA < lenB ? lenA : lenB;
    int idx = r0 * LSN + c0;
    float acc = 0.f;
    #pragma unroll 8
    for (int s = 0; s < len; ++s) {
        acc += buf[idx];
        buf[idx] = acc;
        idx += LSN + 1;
    }
    Tt[(c0 - r0 + (R - 1)) * NCH + q] = acc;
}

// S3: register prefix-scan of chunk totals -> O[q][d]
template<int R, int NCH, int OB>
__device__ __forceinline__ void diag_offsets_body(int xblk) {
    const float* Tt = OB ? g_T2t : g_T1t;
    float (*O)[DMAX] = OB ? g_O2 : g_O1;
    int d = xblk * 256 + threadIdx.x;
    if (d >= R + LSN - 1) return;
    int dd = d - (R - 1);
    float t[NCH];
    const float4* p = reinterpret_cast<const float4*>(Tt + d * NCH);
    #pragma unroll
    for (int i = 0; i < NCH / 4; ++i) {
        float4 v = p[i];
        t[4 * i + 0] = v.x; t[4 * i + 1] = v.y;
        t[4 * i + 2] = v.z; t[4 * i + 3] = v.w;
    }
    float acc = 0.f;
    #pragma unroll
    for (int q = 0; q < NCH; ++q) {
        O[q][d] = acc;
        int rt = q * DCH, rb = rt + DCH - 1;
        if ((rt + dd < LSN) && (rb + dd >= 0)) acc += t[q];
    }
}

// S4/S5: apply GEMM: OUT(64 x N) = A(64 x KT) @ C, C[r,c] = buf[r,c] + O[r/DCH][c-r+R-1]
template<int LAYER>
__device__ __forceinline__ void gemm64_body(int jblk, int kblk,
                                            float (*shA)[36], float (*shB)[68]) {
    constexpr int N  = (LAYER == 1) ? LSN : FCN;
    constexpr int KT = (LAYER == 1) ? NIN : LSN;
    constexpr int KC = (LAYER == 1) ? KC1 : KC2;
    constexpr int R  = (LAYER == 1) ? NIN : FCN;
    constexpr int BT = (LAYER == 1) ? 0 : 1;
    const float* A = (LAYER == 1) ? g_z1 : g_z2;
    const float* B = (LAYER == 1) ? g_buf1 : g_buf2;
    float (*O)[DMAX] = (LAYER == 1) ? g_O1 : g_O2;
    float* OUT = (LAYER == 1) ? g_y1p : g_y2p;
    int j0 = jblk * 64;
    int k0 = kblk * KC;
    int tid = threadIdx.x;
    int tx = tid & 15, ty = tid >> 4;
    float acc[4][4] = {};
    for (int ks = 0; ks < KC; ks += 32) {
        int kb = k0 + ks;
        #pragma unroll
        for (int it = 0; it < 2; ++it) {
            int e = it * 256 + tid;
            int bb = e >> 3, kk4 = (e & 7) * 4;
            *reinterpret_cast<float4*>(&shA[bb][kk4]) =
                *reinterpret_cast<const float4*>(A + bb * KT + kb + kk4);
        }
        if (BT == 0) {
            #pragma unroll
            for (int it = 0; it < 2; ++it) {
                int e = it * 256 + tid;
                int kk = e >> 4, jj4 = (e & 15) * 4;
                int kg = kb + kk;
                float4 v = *reinterpret_cast<const float4*>(B + kg * LSN + j0 + jj4);
                const float* Oq = O[kg >> 5];   // DCH = 32
                int d = (j0 + jj4) - kg + (R - 1);
                v.x += Oq[d]; v.y += Oq[d + 1]; v.z += Oq[d + 2]; v.w += Oq[d + 3];
                *reinterpret_cast<float4*>(&shB[kk][jj4]) = v;
            }
        } else {
            #pragma unroll
            for (int it = 0; it < 2; ++it) {
                int e = it * 256 + tid;
                int jj = e >> 3, kk4 = (e & 7) * 4;
                int jg = j0 + jj;
                float4 v = *reinterpret_cast<const float4*>(B + jg * KT + kb + kk4);
                const float* Oq = O[jg >> 5];
                int d = (kb + kk4) - jg + (R - 1);
                shB[kk4 + 0][jj] = v.x + Oq[d];
                shB[kk4 + 1][jj] = v.y + Oq[d + 1];
                shB[kk4 + 2][jj] = v.z + Oq[d + 2];
                shB[kk4 + 3][jj] = v.w + Oq[d + 3];
            }
        }
        __syncthreads();
        #pragma unroll
        for (int kk = 0; kk < 32; ++kk) {
            float a[4], b[4];
            #pragma unroll
            for (int u = 0; u < 4; ++u) a[u] = shA[ty * 4 + u][kk];
            #pragma unroll
            for (int v = 0; v < 4; ++v) b[v] = shB[kk][tx * 4 + v];
            #pragma unroll
            for (int u = 0; u < 4; ++u)
                #pragma unroll
                for (int v = 0; v < 4; ++v) acc[u][v] += a[u] * b[v];
        }
        __syncthreads();
    }
    #pragma unroll
    for (int u = 0; u < 4; ++u) {
        int bb = ty * 4 + u;
        float4 o = make_float4(acc[u][0], acc[u][1], acc[u][2], acc[u][3]);
        *reinterpret_cast<float4*>(OUT + kblk * (64 * N) + bb * N + j0 + tx * 4) = o;
    }
}

// ---------------- Kernel A: light stages (scan, gemmA, local scans, offsets) ----------------
__global__ void __launch_bounds__(NTHR, 3) kernelA(
    const float* __restrict__ x,
    const float* __restrict__ G1, const float* __restrict__ H1,
    const float* __restrict__ sA1, const float* __restrict__ sB1,
    const float* __restrict__ G2, const float* __restrict__ H2,
    const float* __restrict__ sA2, const float* __restrict__ sB2)
{
    __shared__ float sm[2048];                 // 8 KB pool
    const int bid = blockIdx.x;
    const int tid = threadIdx.x;
    const int G = GRID_A;

    // ---- S0: cumprod scans ----
    for (int t = bid; t < 4; t += G) {
        const float* s = (t == 0) ? sA1 : (t == 1) ? sB1 : (t == 2) ? sA2 : sB2;
        scan_body(t, s, sm);
    }
    grid_barrier(0);

    // ---- S1: gemmA1 (1024) + gemmA2 (512) + z1 prep (64) ----
    {
        float (*shP)[64] = reinterpret_cast<float(*)[64]>(sm);
        float (*shQ)[64] = reinterpret_cast<float(*)[64]>(sm + 1024);
        for (int t = bid; t < 1600; t += G) {
            if (t < 1024) {
                gemmA_body<48, 3, 1>(H1, G1, g_buf1, shP, shQ, (t >> 6) * 64, (t & 63) * 64);
            } else if (t < 1536) {
                int e = t - 1024;
                gemmA_body<16, 5, 7>(G2, H2, g_buf2, shP, shQ, (e >> 6) * 64, (e & 63) * 64);
            } else {
                int b = t - 1536;                       // batch row
                const float4* xv = reinterpret_cast<const float4*>(x + b * NIN);
                float4* zv = reinterpret_cast<float4*>(g_z1 + b * NIN);
                const float4* dv = reinterpret_cast<const float4*>(g_d[2]);
                float4 xx = xv[tid], dd = dv[tid];
                zv[tid] = make_float4(xx.x * dd.x, xx.y * dd.y, xx.z * dd.z, xx.w * dd.w);
            }
        }
    }
    grid_barrier(1);

    // ---- S2: chunk-local diagonal cumsums (544 + 272 = 816 tasks; 2 rounds exactly) ----
    for (int t = bid; t < 17 * NCH1 + 17 * NCH2; t += G) {
        if (t < 17 * NCH1) diag_local_body<NIN, NCH1, 0>(t % 17, t / 17);
        else { int e = t - 17 * NCH1; diag_local_body<FCN, NCH2, 1>(e % 17, e / 17); }
    }
    grid_barrier(2);

    // ---- S3: diagonal offsets (20 + 18 tasks) + counter reset ----
    for (int t = bid; t < 39; t += G) {
        if (t < 20)      diag_offsets_body<NIN, NCH1, 0>(t);
        else if (t < 38) diag_offsets_body<FCN, NCH2, 1>(t - 20);
        else if (tid < 64) g_cnt1[tid] = 0u;
    }
}

// ---------------- Kernel B: heavy stages (gemm64_1+reduce1, gemm64_2, tail) ----------------
__global__ void __launch_bounds__(NTHR, 2) kernelB(
    const float* __restrict__ bias1, const float* __restrict__ bias2,
    const float* __restrict__ W, const float* __restrict__ bl,
    float* __restrict__ out)
{
    __shared__ float sm[4608];                 // 18 KB pool
    __shared__ unsigned int sh_isLast;
    const int bid = blockIdx.x;
    const int tid = threadIdx.x;
    const int G = GRID_B;

    // ---- S4: gemm64_1 (256 tasks, 1 round) with fused per-jblk reduce1 epilogue ----
    {
        float (*shA)[36] = reinterpret_cast<float(*)[36]>(sm);
        float (*shB)[68] = reinterpret_cast<float(*)[68]>(sm + 2304);
        for (int t = bid; t < 256; t += G) {
            int jblk = t & 63, kblk = t >> 6;
            gemm64_body<1>(jblk, kblk, shA, shB);
            __threadfence();
            if (tid == 0)
                sh_isLast = (atomicAdd(&g_cnt1[jblk], 1u) == KCH1 - 1u);
            __syncthreads();
            if (sh_isLast) {
                int j0 = jblk * 64;
                #pragma unroll
                for (int e = 0; e < 4; ++e) {
                    int lin = e * 256 + tid;
                    int b = lin >> 4, jj4 = (lin & 15) * 4;
                    int j = j0 + jj4;
                    float4 s = *reinterpret_cast<const float4*>(&g_y1p[b * LSN + j]);
                    #pragma unroll
                    for (int c = 1; c < KCH1; ++c) {
                        float4 p = *reinterpret_cast<const float4*>(&g_y1p[c * (BATN * LSN) + b * LSN + j]);
                        s.x += p.x; s.y += p.y; s.z += p.z; s.w += p.w;
                    }
                    float4 da = *reinterpret_cast<const float4*>(&g_d[0][j]);
                    float4 db = *reinterpret_cast<const float4*>(&g_d[6][j]);
                    float4 bi = *reinterpret_cast<const float4*>(&bias1[j]);
                    float4 o;
                    o.x = fmaxf(da.x * s.x + bi.x, 0.f) * db.x;
                    o.y = fmaxf(da.y * s.y + bi.y, 0.f) * db.y;
                    o.z = fmaxf(da.z * s.z + bi.z, 0.f) * db.z;
                    o.w = fmaxf(da.w * s.w + bi.w, 0.f) * db.w;
                    *reinterpret_cast<float4*>(&g_z2[b * LSN + j]) = o;
                }
            }
            __syncthreads();
        }
    }
    grid_barrier(3);

    // ---- S5: gemm64_2 (128 tasks, 1 round) ----
    {
        float (*shA)[36] = reinterpret_cast<float(*)[36]>(sm);
        float (*shB)[68] = reinterpret_cast<float(*)[68]>(sm + 2304);
        for (int t = bid; t < 128; t += G)
            gemm64_body<2>(t & 7, t >> 3, shA, shB);
    }
    grid_barrier(4);

    // ---- S6: tail — reduce2 + logits (64 tasks) ----
    for (int t = bid; t < BATN; t += G) {
        float* h = sm;                           // 512 floats
        for (int j = tid; j < FCN; j += NTHR) {
            float s = 0.f;
            #pragma unroll
            for (int c = 0; c < KCH2; ++c) s += g_y2p[c * (BATN * FCN) + t * FCN + j];
            float v = g_d[4][j] * s + bias2[j];
            h[j] = v > 0.f ? v : 0.f;
        }
        __syncthreads();
        int warp = tid >> 5, lane = tid & 31;
        for (int c = warp; c < NCLS; c += 8) {
            const float* wrow = W + c * FCN;
            float s = 0.f;
            #pragma unroll 4
            for (int j = lane; j < FCN; j += 32) s += h[j] * wrow[j];
            #pragma unroll
            for (int off = 16; off; off >>= 1) s += __shfl_xor_sync(0xffffffffu, s, off);
            if (lane == 0) out[t * NCLS + c] = s + bl[c];
        }
        __syncthreads();
    }
}

// ---------------- launch ----------------
extern "C" void kernel_launch(void* const* d_in, const int* in_sizes, int n_in,
                              void* d_out, int out_size) {
    (void)in_sizes; (void)n_in; (void)out_size;
    const float* x      = (const float*)d_in[0];
    const float* G1     = (const float*)d_in[1];
    const float* H1     = (const float*)d_in[2];
    const float* sA1    = (const float*)d_in[3];
    const float* sB1    = (const float*)d_in[4];
    const float* bias1  = (const float*)d_in[5];
    const float* G2     = (const float*)d_in[6];
    const float* H2     = (const float*)d_in[7];
    const float* sA2    = (const float*)d_in[8];
    const float* sB2    = (const float*)d_in[9];
    const float* bias2  = (const float*)d_in[10];
    const float* W      = (const float*)d_in[11];
    const float* bl     = (const float*)d_in[12];
    float* out = (float*)d_out;

    kernelA<<<GRID_A, NTHR>>>(x, G1, H1, sA1, sB1, G2, H2, sA2, sB2);
    kernelB<<<GRID_B, NTHR>>>(bias1, bias2, W, bl, out);
}